// round 1
// baseline (speedup 1.0000x reference)
#include <cuda_runtime.h>
#include <cuda_bf16.h>

// Problem shape (fixed by setup_inputs)
#define BB 16
#define TT 800
#define VV 4000
#define LL 100
#define SS 201       // 2L+1
#define EP 104       // padded emit row (blank + 100 labels, padded to 104)
#define NEGV (-1e30f)
#define LAMB 0.1f

// Scratch (allocation-free rule: __device__ globals)
__device__ float g_lse[BB * TT];
__device__ float g_emit[(size_t)BB * TT * EP];
__device__ float g_cost[BB];

__inline__ __device__ float warp_max(float v) {
#pragma unroll
    for (int o = 16; o; o >>= 1) v = fmaxf(v, __shfl_xor_sync(0xffffffffu, v, o));
    return v;
}
__inline__ __device__ float warp_sum(float v) {
#pragma unroll
    for (int o = 16; o; o >>= 1) v += __shfl_xor_sync(0xffffffffu, v, o);
    return v;
}

// Kernel 1: per-(b,t) logsumexp over V + gather of the <=101 needed vocab
// entries into g_emit. One CTA per (b,t) row. Single pass over HBM.
__global__ __launch_bounds__(256) void lse_gather_kernel(
    const float* __restrict__ logits, const int* __restrict__ labels) {
    const int bt = blockIdx.x;                 // b*TT + t
    const float* __restrict__ row = logits + (size_t)bt * VV;
    const int tid = threadIdx.x;
    const int lane = tid & 31, wid = tid >> 5;

    // Load 4 float4 per thread (VV/4 = 1000 float4, 256 threads)
    float4 v[4];
    bool ok[4];
    float mx = NEGV;
#pragma unroll
    for (int i = 0; i < 4; i++) {
        int idx = tid + i * 256;
        ok[i] = (idx < VV / 4);
        if (ok[i]) {
            v[i] = reinterpret_cast<const float4*>(row)[idx];
            mx = fmaxf(mx, fmaxf(fmaxf(v[i].x, v[i].y), fmaxf(v[i].z, v[i].w)));
        }
    }

    __shared__ float smax[8];
    __shared__ float ssum[8];
    mx = warp_max(mx);
    if (lane == 0) smax[wid] = mx;
    __syncthreads();
    mx = smax[0];
#pragma unroll
    for (int i = 1; i < 8; i++) mx = fmaxf(mx, smax[i]);

    float s = 0.0f;
#pragma unroll
    for (int i = 0; i < 4; i++) {
        if (ok[i]) {
            s += __expf(v[i].x - mx) + __expf(v[i].y - mx) +
                 __expf(v[i].z - mx) + __expf(v[i].w - mx);
        }
    }
    s = warp_sum(s);
    if (lane == 0) ssum[wid] = s;
    __syncthreads();
    s = ssum[0];
#pragma unroll
    for (int i = 1; i < 8; i++) s += ssum[i];

    const float lse = mx + __logf(s);
    if (tid == 0) g_lse[bt] = lse;

    // Gather: emit[k] = logits[row, ext_k] - lse, k=0 blank, k=1..100 labels
    const int b = bt / TT;
    if (tid <= LL) {
        int vv = (tid == 0) ? 0 : labels[b * LL + tid - 1];
        g_emit[(size_t)bt * EP + tid] = __ldg(row + vv) - lse;
    }
}

// Kernel 2: CTC forward DP, one CTA per batch element. Also computes
// costs_den = sum_{t<len} lse[b,t], and writes per-batch cost.
#define CHUNK 16
__global__ __launch_bounds__(256) void ctc_dp_kernel(
    const int* __restrict__ labels,
    const int* __restrict__ input_lengths,
    const int* __restrict__ label_lengths) {
    const int b = blockIdx.x;
    const int tid = threadIdx.x;
    const int lane = tid & 31, wid = tid >> 5;

    __shared__ float bufA[SS + 8];
    __shared__ float bufB[SS + 8];
    __shared__ float esh[CHUNK * EP];
    __shared__ float rr[8];
    __shared__ float s_den;

    const int len = input_lengths[b];

    // ---- costs_den = sum_{t < len} lse[b,t] ----
    float part = 0.0f;
    for (int t = tid; t < TT; t += 256)
        if (t < len) part += g_lse[b * TT + t];
    part = warp_sum(part);
    if (lane == 0) rr[wid] = part;
    __syncthreads();
    if (tid == 0) {
        float d = rr[0];
#pragma unroll
        for (int i = 1; i < 8; i++) d += rr[i];
        s_den = d;
    }
    __syncthreads();

    // ---- per-state constants ----
    bool allow = false;
    int k = 0;
    if (tid < SS) {
        if (tid & 1) {
            k = 1 + (tid >> 1);
            if (tid >= 3)
                allow = labels[b * LL + (tid >> 1)] != labels[b * LL + (tid >> 1) - 1];
        } else {
            k = 0;
        }
    }

    float* A = bufA;
    float* Bn = bufB;
    const float* __restrict__ eb = g_emit + (size_t)b * TT * EP;

    for (int c = 0; c < TT / CHUNK; c++) {
        // Stage a chunk of emit rows into shared (contiguous copy)
        for (int i = tid; i < CHUNK * EP; i += 256)
            esh[i] = eb[(size_t)c * CHUNK * EP + i];
        __syncthreads();

#pragma unroll 4
        for (int tt = 0; tt < CHUNK; tt++) {
            const int t = c * CHUNK + tt;
            if (t == 0) {
                if (tid < SS) A[tid] = (tid < 2) ? esh[k] : NEGV;
                __syncthreads();
                continue;
            }
            if (tid < SS) {
                const float cur = A[tid];
                float r;
                if (t < len) {
                    const float a1 = (tid >= 1) ? A[tid - 1] : NEGV;
                    const float a2 = allow ? A[tid - 2] : NEGV;
                    const float m = fmaxf(cur, fmaxf(a1, a2));
                    const float sum =
                        __expf(cur - m) + __expf(a1 - m) + __expf(a2 - m);
                    r = m + __logf(sum) + esh[tt * EP + k];
                } else {
                    r = cur;
                }
                Bn[tid] = r;
            }
            __syncthreads();
            float* tmp = A; A = Bn; Bn = tmp;
        }
    }

    if (tid == 0) {
        const int e = 2 * label_lengths[b];
        const float ae = A[e];
        const float ae1 = A[e - 1];
        const float m = fmaxf(ae, ae1);
        const float nll = -(m + __logf(__expf(ae - m) + __expf(ae1 - m)));
        g_cost[b] = s_den - (1.0f + LAMB) * nll;
    }
}

// Kernel 3: final mean
__global__ void finalize_kernel(float* __restrict__ out) {
    if (threadIdx.x == 0) {
        float s = 0.0f;
#pragma unroll
        for (int i = 0; i < BB; i++) s += g_cost[i];
        out[0] = s / (float)BB;
    }
}

extern "C" void kernel_launch(void* const* d_in, const int* in_sizes, int n_in,
                              void* d_out, int out_size) {
    const float* logits = (const float*)d_in[0];
    const int* labels = (const int*)d_in[1];
    const int* input_lengths = (const int*)d_in[2];
    const int* label_lengths = (const int*)d_in[3];
    float* out = (float*)d_out;

    lse_gather_kernel<<<BB * TT, 256>>>(logits, labels);
    ctc_dp_kernel<<<BB, 256>>>(labels, input_lengths, label_lengths);
    finalize_kernel<<<1, 32>>>(out);
}